// round 2
// baseline (speedup 1.0000x reference)
#include <cuda_runtime.h>
#include <cuda_bf16.h>

#define B_ 256
#define L_ 1026
#define D_ 1280
#define E_ 300
#define H_ 256
#define C_ 1580   // D_+E_

// ---- scratch (device globals; no allocation allowed) ----
__device__ float g_pooled[B_ * D_];
__device__ float g_inv[B_];
__device__ float g_x1[B_ * D_];
__device__ float g_q[B_ * E_];
__device__ float g_attn[B_ * B_];
__device__ float g_f1[B_ * E_];
__device__ float g_f2[B_ * D_];
__device__ float g_comb[B_ * C_];
__device__ float g_h[B_ * H_];

// ------------------------------------------------------------------
// zero pooled accumulator + compute 1/count per batch row
// ------------------------------------------------------------------
__global__ void zero_and_inv_kernel(const int* __restrict__ lens) {
    int i = blockIdx.x * blockDim.x + threadIdx.x;
    if (i < B_ * D_) g_pooled[i] = 0.f;
    if (i < B_) {
        int len = lens[i];
        g_inv[i] = 1.f / fmaxf((float)(len - 2), 1.f);
    }
}

// ------------------------------------------------------------------
// ragged masked sum pooling: grid (B, ceil(L/TL)), block 320 (= D/4)
// ------------------------------------------------------------------
#define TL 128
__global__ void pool_kernel(const float* __restrict__ tok,
                            const int* __restrict__ lens) {
    int b = blockIdx.x;
    int len = lens[b];
    int l0 = blockIdx.y * TL;
    if (l0 < 1) l0 = 1;
    int l1 = min((int)(blockIdx.y + 1) * TL, len - 1);
    if (l0 >= l1) return;

    int d4 = threadIdx.x;  // 0..319
    const float4* base = reinterpret_cast<const float4*>(tok)
                       + (size_t)b * L_ * (D_ / 4) + d4;
    float4 acc = make_float4(0.f, 0.f, 0.f, 0.f);
    for (int l = l0; l < l1; l++) {
        float4 v = base[(size_t)l * (D_ / 4)];
        acc.x += v.x; acc.y += v.y; acc.z += v.z; acc.w += v.w;
    }
    float* o = g_pooled + b * D_ + d4 * 4;
    atomicAdd(o + 0, acc.x);
    atomicAdd(o + 1, acc.y);
    atomicAdd(o + 2, acc.z);
    atomicAdd(o + 3, acc.w);
}

// ------------------------------------------------------------------
// generic tiled SGEMM: C[M,N] = act( rscale[m] * A_eff @ B_eff + bias )
//   A_eff(m,k) = TA ? A[k*lda+m] : A[m*lda+k]
//   B_eff(k,n) = TB ? B[n*ldb+k] : B[k*ldb+n]
// BM=BN=64, BK=16, 256 threads, 4x4 microtile.
// ------------------------------------------------------------------
template <int TA, int TB, int RELU, int SCALEA>
__global__ void sgemm_kernel(const float* __restrict__ A,
                             const float* __restrict__ B,
                             const float* __restrict__ bias,
                             const float* __restrict__ rscale,
                             float* __restrict__ C,
                             int M, int N, int K, int lda, int ldb) {
    __shared__ float As[16][64];
    __shared__ float Bs[16][64];

    int t = threadIdx.x;
    int bm = blockIdx.y * 64;
    int bn = blockIdx.x * 64;
    int tx = t & 15;   // N dir
    int ty = t >> 4;   // M dir

    float acc[4][4];
#pragma unroll
    for (int i = 0; i < 4; i++)
#pragma unroll
        for (int j = 0; j < 4; j++) acc[i][j] = 0.f;

    for (int k0 = 0; k0 < K; k0 += 16) {
        if (!TA) {
            int mm = t >> 2;
            int kk4 = (t & 3) * 4;
            float4 v = make_float4(0.f, 0.f, 0.f, 0.f);
            if (k0 + kk4 < K)
                v = *reinterpret_cast<const float4*>(
                        &A[(size_t)(bm + mm) * lda + k0 + kk4]);
            As[kk4 + 0][mm] = v.x;
            As[kk4 + 1][mm] = v.y;
            As[kk4 + 2][mm] = v.z;
            As[kk4 + 3][mm] = v.w;
        } else {
            int kk = t >> 4;
            int mm4 = (t & 15) * 4;
            float4 v = make_float4(0.f, 0.f, 0.f, 0.f);
            if (k0 + kk < K)
                v = *reinterpret_cast<const float4*>(
                        &A[(size_t)(k0 + kk) * lda + bm + mm4]);
            *reinterpret_cast<float4*>(&As[kk][mm4]) = v;
        }
        if (!TB) {
            int kk = t >> 4;
            int nn4 = (t & 15) * 4;
            float4 v = make_float4(0.f, 0.f, 0.f, 0.f);
            if (k0 + kk < K && bn + nn4 < N)
                v = *reinterpret_cast<const float4*>(
                        &B[(size_t)(k0 + kk) * ldb + bn + nn4]);
            *reinterpret_cast<float4*>(&Bs[kk][nn4]) = v;
        } else {
            int nn = t >> 2;
            int kk4 = (t & 3) * 4;
            float4 v = make_float4(0.f, 0.f, 0.f, 0.f);
            if (bn + nn < N && k0 + kk4 < K)
                v = *reinterpret_cast<const float4*>(
                        &B[(size_t)(bn + nn) * ldb + k0 + kk4]);
            Bs[kk4 + 0][nn] = v.x;
            Bs[kk4 + 1][nn] = v.y;
            Bs[kk4 + 2][nn] = v.z;
            Bs[kk4 + 3][nn] = v.w;
        }
        __syncthreads();

#pragma unroll
        for (int kk = 0; kk < 16; kk++) {
            float4 av = *reinterpret_cast<float4*>(&As[kk][ty * 4]);
            float4 bv = *reinterpret_cast<float4*>(&Bs[kk][tx * 4]);
            float a[4] = {av.x, av.y, av.z, av.w};
            float b[4] = {bv.x, bv.y, bv.z, bv.w};
#pragma unroll
            for (int i = 0; i < 4; i++)
#pragma unroll
                for (int j = 0; j < 4; j++) acc[i][j] += a[i] * b[j];
        }
        __syncthreads();
    }

#pragma unroll
    for (int i = 0; i < 4; i++) {
        int gm = bm + ty * 4 + i;
        float sc = SCALEA ? rscale[gm] : 1.f;
#pragma unroll
        for (int j = 0; j < 4; j++) {
            int gn = bn + tx * 4 + j;
            if (gn < N) {
                float v = acc[i][j] * sc;
                if (bias) v += bias[gn];
                if (RELU) v = fmaxf(v, 0.f);
                C[(size_t)gm * N + gn] = v;
            }
        }
    }
}

// ------------------------------------------------------------------
// row softmax in-place: one block (256 threads) per row
// ------------------------------------------------------------------
__global__ void row_softmax_kernel(float* __restrict__ X, int N) {
    int r = blockIdx.x;
    float* x = X + (size_t)r * N;
    int t = threadIdx.x;
    __shared__ float red[8];

    float m = -1e30f;
    for (int i = t; i < N; i += 256) m = fmaxf(m, x[i]);
#pragma unroll
    for (int o = 16; o > 0; o >>= 1) m = fmaxf(m, __shfl_xor_sync(0xffffffffu, m, o));
    if ((t & 31) == 0) red[t >> 5] = m;
    __syncthreads();
    if (t < 8) {
        float v = red[t];
#pragma unroll
        for (int o = 4; o > 0; o >>= 1) v = fmaxf(v, __shfl_xor_sync(0xffu, v, o));
        if (t == 0) red[0] = v;
    }
    __syncthreads();
    m = red[0];
    __syncthreads();

    float s = 0.f;
    for (int i = t; i < N; i += 256) {
        float e = __expf(x[i] - m);
        x[i] = e;
        s += e;
    }
#pragma unroll
    for (int o = 16; o > 0; o >>= 1) s += __shfl_xor_sync(0xffffffffu, s, o);
    if ((t & 31) == 0) red[t >> 5] = s;
    __syncthreads();
    if (t < 8) {
        float v = red[t];
#pragma unroll
        for (int o = 4; o > 0; o >>= 1) v += __shfl_xor_sync(0xffu, v, o);
        if (t == 0) red[0] = v;
    }
    __syncthreads();
    float inv = 1.f / red[0];
    for (int i = t; i < N; i += 256) x[i] *= inv;
}

// ------------------------------------------------------------------
// combined[b, :D] = x1*(f2+1); combined[b, D:] = x2*(f1+1)
// ------------------------------------------------------------------
__global__ void combine_kernel(const float* __restrict__ x2) {
    int idx = blockIdx.x * blockDim.x + threadIdx.x;
    if (idx >= B_ * C_) return;
    int b = idx / C_;
    int j = idx - b * C_;
    float v;
    if (j < D_) {
        float a = g_x1[b * D_ + j];
        v = a * (g_f2[b * D_ + j] + 1.f);
    } else {
        int e = j - D_;
        float a = x2[b * E_ + e];
        v = a * (g_f1[b * E_ + e] + 1.f);
    }
    g_comb[idx] = v;
}

// ------------------------------------------------------------------
// out[b] = sum_h g_h[b,h] * W2[h] + b2[0]  (block per b, 256 threads)
// ------------------------------------------------------------------
__global__ void final_kernel(const float* __restrict__ W2,
                             const float* __restrict__ b2,
                             float* __restrict__ out) {
    int b = blockIdx.x;
    int t = threadIdx.x;
    __shared__ float red[8];
    float v = g_h[b * H_ + t] * W2[t];
#pragma unroll
    for (int o = 16; o > 0; o >>= 1) v += __shfl_xor_sync(0xffffffffu, v, o);
    if ((t & 31) == 0) red[t >> 5] = v;
    __syncthreads();
    if (t < 8) {
        float s = red[t];
#pragma unroll
        for (int o = 4; o > 0; o >>= 1) s += __shfl_xor_sync(0xffu, s, o);
        if (t == 0) out[b] = s + b2[0];
    }
}

// ------------------------------------------------------------------
extern "C" void kernel_launch(void* const* d_in, const int* in_sizes, int n_in,
                              void* d_out, int out_size) {
    const float* token_reps = (const float*)d_in[0];
    const int*   batch_lens = (const int*)d_in[1];
    const float* mol_repr   = (const float*)d_in[2];
    const float* W_prot     = (const float*)d_in[3];
    const float* b_prot     = (const float*)d_in[4];
    const float* W_attn     = (const float*)d_in[5];
    const float* b_attn     = (const float*)d_in[6];
    const float* W_fc1      = (const float*)d_in[7];
    const float* b_fc1      = (const float*)d_in[8];
    const float* W_fc2      = (const float*)d_in[9];
    const float* b_fc2      = (const float*)d_in[10];
    float* out = (float*)d_out;

    // Resolve device addresses of __device__ scratch (host-side symbol
    // lookup; no stream ops, graph-capture safe).
    float *p_pooled, *p_inv, *p_x1, *p_q, *p_attn, *p_f1, *p_f2, *p_comb, *p_h;
    cudaGetSymbolAddress((void**)&p_pooled, g_pooled);
    cudaGetSymbolAddress((void**)&p_inv,    g_inv);
    cudaGetSymbolAddress((void**)&p_x1,     g_x1);
    cudaGetSymbolAddress((void**)&p_q,      g_q);
    cudaGetSymbolAddress((void**)&p_attn,   g_attn);
    cudaGetSymbolAddress((void**)&p_f1,     g_f1);
    cudaGetSymbolAddress((void**)&p_f2,     g_f2);
    cudaGetSymbolAddress((void**)&p_comb,   g_comb);
    cudaGetSymbolAddress((void**)&p_h,      g_h);

    // 1) zero accumulators + inverse counts
    zero_and_inv_kernel<<<(B_ * D_ + 255) / 256, 256>>>(batch_lens);

    // 2) ragged masked sum pool
    {
        dim3 grid(B_, (L_ + TL - 1) / TL);
        pool_kernel<<<grid, D_ / 4>>>(token_reps, batch_lens);
    }

    // 3) x1 = relu((pooled/count) @ W_prot + b_prot)   [256,1280]
    sgemm_kernel<0, 0, 1, 1><<<dim3(D_ / 64, B_ / 64), 256>>>(
        p_pooled, W_prot, b_prot, p_inv, p_x1, B_, D_, D_, D_, D_);

    // 4) q = x1 @ W_attn + b_attn   [256,300]
    sgemm_kernel<0, 0, 0, 0><<<dim3((E_ + 63) / 64, B_ / 64), 256>>>(
        p_x1, W_attn, b_attn, nullptr, p_q, B_, E_, D_, D_, E_);

    // 5) attn = softmax(q @ x2^T)   [256,256]
    sgemm_kernel<0, 1, 0, 0><<<dim3(B_ / 64, B_ / 64), 256>>>(
        p_q, mol_repr, nullptr, nullptr, p_attn, B_, B_, E_, E_, E_);
    row_softmax_kernel<<<B_, 256>>>(p_attn, B_);

    // 6) fused_x1 = softmax(attn @ x2)   [256,300]
    sgemm_kernel<0, 0, 0, 0><<<dim3((E_ + 63) / 64, B_ / 64), 256>>>(
        p_attn, mol_repr, nullptr, nullptr, p_f1, B_, E_, B_, B_, E_);
    row_softmax_kernel<<<B_, 256>>>(p_f1, E_);

    // 7) fused_x2 = softmax(attn^T @ x1)   [256,1280]
    sgemm_kernel<1, 0, 0, 0><<<dim3(D_ / 64, B_ / 64), 256>>>(
        p_attn, p_x1, nullptr, nullptr, p_f2, B_, D_, B_, B_, D_);
    row_softmax_kernel<<<B_, 256>>>(p_f2, D_);

    // 8) combined = [x1*(f2+1), x2*(f1+1)]   [256,1580]
    combine_kernel<<<(B_ * C_ + 255) / 256, 256>>>(mol_repr);

    // 9) h = relu(combined @ W_fc1 + b_fc1)   [256,256]
    sgemm_kernel<0, 0, 1, 0><<<dim3(H_ / 64, B_ / 64), 256>>>(
        p_comb, W_fc1, b_fc1, nullptr, p_h, B_, H_, C_, C_, H_);

    // 10) out = h @ W_fc2 + b_fc2   [256,1]
    final_kernel<<<B_, 256>>>(W_fc2, b_fc2, out);
}

// round 3
// speedup vs baseline: 2.1461x; 2.1461x over previous
#include <cuda_runtime.h>
#include <cuda_bf16.h>

#define B_ 256
#define L_ 1026
#define D_ 1280
#define E_ 300
#define H_ 256
#define C_ 1580   // D_+E_

// ---- scratch (device globals; no allocation allowed) ----
__device__ float g_pooled[B_ * D_];
__device__ float g_inv[B_];
__device__ float g_x1[B_ * D_];
__device__ float g_q[B_ * E_];
__device__ float g_attn[B_ * B_];
__device__ float g_f1[B_ * E_];
__device__ float g_f2[B_ * D_];
__device__ float g_comb[B_ * C_];
__device__ float g_h[B_ * H_];

// ------------------------------------------------------------------
// zero ALL accumulators in one pass + compute 1/count per batch row
// grid covers 327680 elements (largest buffer B*D)
// ------------------------------------------------------------------
__global__ void zero_all_kernel(const int* __restrict__ lens) {
    int i = blockIdx.x * blockDim.x + threadIdx.x;
    if (i < B_ * D_) { g_pooled[i] = 0.f; g_x1[i] = 0.f; g_f2[i] = 0.f; }
    if (i < B_ * E_) { g_q[i] = 0.f; g_f1[i] = 0.f; }
    if (i < B_ * B_) { g_attn[i] = 0.f; }
    if (i < B_ * H_) { g_h[i] = 0.f; }
    if (i < B_) {
        int len = lens[i];
        g_inv[i] = 1.f / fmaxf((float)(len - 2), 1.f);
    }
}

// ------------------------------------------------------------------
// ragged masked sum pooling: grid (B, ceil(L/TL)), block 320 (= D/4)
// ------------------------------------------------------------------
#define TL 128
__global__ void pool_kernel(const float* __restrict__ tok,
                            const int* __restrict__ lens) {
    int b = blockIdx.x;
    int len = lens[b];
    int l0 = blockIdx.y * TL;
    if (l0 < 1) l0 = 1;
    int l1 = min((int)(blockIdx.y + 1) * TL, len - 1);
    if (l0 >= l1) return;

    int d4 = threadIdx.x;  // 0..319
    const float4* base = reinterpret_cast<const float4*>(tok)
                       + (size_t)b * L_ * (D_ / 4) + d4;
    float4 acc = make_float4(0.f, 0.f, 0.f, 0.f);
    for (int l = l0; l < l1; l++) {
        float4 v = base[(size_t)l * (D_ / 4)];
        acc.x += v.x; acc.y += v.y; acc.z += v.z; acc.w += v.w;
    }
    float* o = g_pooled + b * D_ + d4 * 4;
    atomicAdd(o + 0, acc.x);
    atomicAdd(o + 1, acc.y);
    atomicAdd(o + 2, acc.z);
    atomicAdd(o + 3, acc.w);
}

// ------------------------------------------------------------------
// split-K tiled SGEMM, partials accumulated via atomicAdd into C.
//   C[M,N] += sum_{k in this split} (SCALEA? rscale[m]:1) * A_eff(m,k)*B_eff(k,n)
//   A_eff(m,k) = TA ? A[k*lda+m] : A[m*lda+k]
//   B_eff(k,n) = TB ? B[n*ldb+k] : B[k*ldb+n]
// BM=BN=64, BK=16, 256 threads, 4x4 microtile.
// grid.z = number of K splits; each split owns tiles_per_split k-tiles of 16.
// C must be pre-zeroed. Bias/activation applied by separate epilogue.
// ------------------------------------------------------------------
template <int TA, int TB, int SCALEA>
__global__ void sgemm_splitk_kernel(const float* __restrict__ A,
                                    const float* __restrict__ B,
                                    const float* __restrict__ rscale,
                                    float* __restrict__ C,
                                    int M, int N, int K, int lda, int ldb,
                                    int tiles_per_split) {
    __shared__ float As[16][64];
    __shared__ float Bs[16][64];

    int k_begin = blockIdx.z * tiles_per_split * 16;
    if (k_begin >= K) return;
    int k_end = min(k_begin + tiles_per_split * 16, K);

    int t = threadIdx.x;
    int bm = blockIdx.y * 64;
    int bn = blockIdx.x * 64;
    int tx = t & 15;   // N dir
    int ty = t >> 4;   // M dir

    float acc[4][4];
#pragma unroll
    for (int i = 0; i < 4; i++)
#pragma unroll
        for (int j = 0; j < 4; j++) acc[i][j] = 0.f;

    for (int k0 = k_begin; k0 < k_end; k0 += 16) {
        if (!TA) {
            int mm = t >> 2;
            int kk4 = (t & 3) * 4;
            float4 v = make_float4(0.f, 0.f, 0.f, 0.f);
            if (k0 + kk4 < K)
                v = *reinterpret_cast<const float4*>(
                        &A[(size_t)(bm + mm) * lda + k0 + kk4]);
            As[kk4 + 0][mm] = v.x;
            As[kk4 + 1][mm] = v.y;
            As[kk4 + 2][mm] = v.z;
            As[kk4 + 3][mm] = v.w;
        } else {
            int kk = t >> 4;
            int mm4 = (t & 15) * 4;
            float4 v = make_float4(0.f, 0.f, 0.f, 0.f);
            if (k0 + kk < K)
                v = *reinterpret_cast<const float4*>(
                        &A[(size_t)(k0 + kk) * lda + bm + mm4]);
            *reinterpret_cast<float4*>(&As[kk][mm4]) = v;
        }
        if (!TB) {
            int kk = t >> 4;
            int nn4 = (t & 15) * 4;
            float4 v = make_float4(0.f, 0.f, 0.f, 0.f);
            if (k0 + kk < K && bn + nn4 < N)
                v = *reinterpret_cast<const float4*>(
                        &B[(size_t)(k0 + kk) * ldb + bn + nn4]);
            *reinterpret_cast<float4*>(&Bs[kk][nn4]) = v;
        } else {
            int nn = t >> 2;
            int kk4 = (t & 3) * 4;
            float4 v = make_float4(0.f, 0.f, 0.f, 0.f);
            if (bn + nn < N && k0 + kk4 < K)
                v = *reinterpret_cast<const float4*>(
                        &B[(size_t)(bn + nn) * ldb + k0 + kk4]);
            Bs[kk4 + 0][nn] = v.x;
            Bs[kk4 + 1][nn] = v.y;
            Bs[kk4 + 2][nn] = v.z;
            Bs[kk4 + 3][nn] = v.w;
        }
        __syncthreads();

#pragma unroll
        for (int kk = 0; kk < 16; kk++) {
            float4 av = *reinterpret_cast<float4*>(&As[kk][ty * 4]);
            float4 bv = *reinterpret_cast<float4*>(&Bs[kk][tx * 4]);
            float a[4] = {av.x, av.y, av.z, av.w};
            float b[4] = {bv.x, bv.y, bv.z, bv.w};
#pragma unroll
            for (int i = 0; i < 4; i++)
#pragma unroll
                for (int j = 0; j < 4; j++) acc[i][j] += a[i] * b[j];
        }
        __syncthreads();
    }

#pragma unroll
    for (int i = 0; i < 4; i++) {
        int gm = bm + ty * 4 + i;
        float sc = SCALEA ? rscale[gm] : 1.f;
#pragma unroll
        for (int j = 0; j < 4; j++) {
            int gn = bn + tx * 4 + j;
            if (gn < N) atomicAdd(&C[(size_t)gm * N + gn], acc[i][j] * sc);
        }
    }
}

// ------------------------------------------------------------------
// epilogue: X[m,n] = act(X[m,n] + bias[n])  over M*N elements
// ------------------------------------------------------------------
template <int RELU>
__global__ void bias_act_kernel(float* __restrict__ X,
                                const float* __restrict__ bias,
                                int MN, int N) {
    int i = blockIdx.x * blockDim.x + threadIdx.x;
    if (i >= MN) return;
    int n = i % N;
    float v = X[i] + bias[n];
    if (RELU) v = fmaxf(v, 0.f);
    X[i] = v;
}

// ------------------------------------------------------------------
// row softmax in-place: one block (256 threads) per row
// ------------------------------------------------------------------
__global__ void row_softmax_kernel(float* __restrict__ X, int N) {
    int r = blockIdx.x;
    float* x = X + (size_t)r * N;
    int t = threadIdx.x;
    __shared__ float red[8];

    float m = -1e30f;
    for (int i = t; i < N; i += 256) m = fmaxf(m, x[i]);
#pragma unroll
    for (int o = 16; o > 0; o >>= 1) m = fmaxf(m, __shfl_xor_sync(0xffffffffu, m, o));
    if ((t & 31) == 0) red[t >> 5] = m;
    __syncthreads();
    if (t < 8) {
        float v = red[t];
#pragma unroll
        for (int o = 4; o > 0; o >>= 1) v = fmaxf(v, __shfl_xor_sync(0xffu, v, o));
        if (t == 0) red[0] = v;
    }
    __syncthreads();
    m = red[0];
    __syncthreads();

    float s = 0.f;
    for (int i = t; i < N; i += 256) {
        float e = __expf(x[i] - m);
        x[i] = e;
        s += e;
    }
#pragma unroll
    for (int o = 16; o > 0; o >>= 1) s += __shfl_xor_sync(0xffffffffu, s, o);
    if ((t & 31) == 0) red[t >> 5] = s;
    __syncthreads();
    if (t < 8) {
        float v = red[t];
#pragma unroll
        for (int o = 4; o > 0; o >>= 1) v += __shfl_xor_sync(0xffu, v, o);
        if (t == 0) red[0] = v;
    }
    __syncthreads();
    float inv = 1.f / red[0];
    for (int i = t; i < N; i += 256) x[i] *= inv;
}

// ------------------------------------------------------------------
// combined[b, :D] = x1*(f2+1); combined[b, D:] = x2*(f1+1)
// ------------------------------------------------------------------
__global__ void combine_kernel(const float* __restrict__ x2) {
    int idx = blockIdx.x * blockDim.x + threadIdx.x;
    if (idx >= B_ * C_) return;
    int b = idx / C_;
    int j = idx - b * C_;
    float v;
    if (j < D_) {
        float a = g_x1[b * D_ + j];
        v = a * (g_f2[b * D_ + j] + 1.f);
    } else {
        int e = j - D_;
        float a = x2[b * E_ + e];
        v = a * (g_f1[b * E_ + e] + 1.f);
    }
    g_comb[idx] = v;
}

// ------------------------------------------------------------------
// out[b] = sum_h relu(g_h[b,h] + b_fc1[h]) * W2[h] + b2[0]
// (fc1 bias+relu folded in; block per b, 256 threads = H)
// ------------------------------------------------------------------
__global__ void final_kernel(const float* __restrict__ b1,
                             const float* __restrict__ W2,
                             const float* __restrict__ b2,
                             float* __restrict__ out) {
    int b = blockIdx.x;
    int t = threadIdx.x;
    __shared__ float red[8];
    float v = fmaxf(g_h[b * H_ + t] + b1[t], 0.f) * W2[t];
#pragma unroll
    for (int o = 16; o > 0; o >>= 1) v += __shfl_xor_sync(0xffffffffu, v, o);
    if ((t & 31) == 0) red[t >> 5] = v;
    __syncthreads();
    if (t < 8) {
        float s = red[t];
#pragma unroll
        for (int o = 4; o > 0; o >>= 1) s += __shfl_xor_sync(0xffu, s, o);
        if (t == 0) out[b] = s + b2[0];
    }
}

// ------------------------------------------------------------------
static inline int ceil_div(int a, int b) { return (a + b - 1) / b; }

extern "C" void kernel_launch(void* const* d_in, const int* in_sizes, int n_in,
                              void* d_out, int out_size) {
    const float* token_reps = (const float*)d_in[0];
    const int*   batch_lens = (const int*)d_in[1];
    const float* mol_repr   = (const float*)d_in[2];
    const float* W_prot     = (const float*)d_in[3];
    const float* b_prot     = (const float*)d_in[4];
    const float* W_attn     = (const float*)d_in[5];
    const float* b_attn     = (const float*)d_in[6];
    const float* W_fc1      = (const float*)d_in[7];
    const float* b_fc1      = (const float*)d_in[8];
    const float* W_fc2      = (const float*)d_in[9];
    const float* b_fc2      = (const float*)d_in[10];
    float* out = (float*)d_out;

    float *p_pooled, *p_inv, *p_x1, *p_q, *p_attn, *p_f1, *p_f2, *p_comb, *p_h;
    cudaGetSymbolAddress((void**)&p_pooled, g_pooled);
    cudaGetSymbolAddress((void**)&p_inv,    g_inv);
    cudaGetSymbolAddress((void**)&p_x1,     g_x1);
    cudaGetSymbolAddress((void**)&p_q,      g_q);
    cudaGetSymbolAddress((void**)&p_attn,   g_attn);
    cudaGetSymbolAddress((void**)&p_f1,     g_f1);
    cudaGetSymbolAddress((void**)&p_f2,     g_f2);
    cudaGetSymbolAddress((void**)&p_comb,   g_comb);
    cudaGetSymbolAddress((void**)&p_h,      g_h);

    // 1) zero all accumulators + inverse counts
    zero_all_kernel<<<ceil_div(B_ * D_, 256), 256>>>(batch_lens);

    // 2) ragged masked sum pool
    {
        dim3 grid(B_, ceil_div(L_, TL));
        pool_kernel<<<grid, D_ / 4>>>(token_reps, batch_lens);
    }

    // 3) x1 = relu((pooled/count) @ W_prot + b_prot)  [256,1280], K=1280
    {
        int tiles = ceil_div(D_, 16);            // 80
        int tps = ceil_div(tiles, 4);            // 20 -> 4 splits
        dim3 grid(D_ / 64, B_ / 64, ceil_div(tiles, tps));   // 20x4x4 = 320
        sgemm_splitk_kernel<0, 0, 1><<<grid, 256>>>(
            p_pooled, W_prot, p_inv, p_x1, B_, D_, D_, D_, D_, tps);
        bias_act_kernel<1><<<ceil_div(B_ * D_, 256), 256>>>(p_x1, b_prot, B_ * D_, D_);
    }

    // 4) q = x1 @ W_attn + b_attn  [256,300], K=1280
    {
        int tiles = ceil_div(D_, 16);            // 80
        int tps = 8;                              // -> 10 splits
        dim3 grid(ceil_div(E_, 64), B_ / 64, ceil_div(tiles, tps));  // 5x4x10 = 200
        sgemm_splitk_kernel<0, 0, 0><<<grid, 256>>>(
            p_x1, W_attn, nullptr, p_q, B_, E_, D_, D_, E_, tps);
        bias_act_kernel<0><<<ceil_div(B_ * E_, 256), 256>>>(p_q, b_attn, B_ * E_, E_);
    }

    // 5) attn = softmax(q @ x2^T)  [256,256], K=300
    {
        int tiles = ceil_div(E_, 16);            // 19
        int tps = 2;                              // -> 10 splits
        dim3 grid(B_ / 64, B_ / 64, ceil_div(tiles, tps));  // 4x4x10 = 160
        sgemm_splitk_kernel<0, 1, 0><<<grid, 256>>>(
            p_q, mol_repr, nullptr, p_attn, B_, B_, E_, E_, E_, tps);
        row_softmax_kernel<<<B_, 256>>>(p_attn, B_);
    }

    // 6) fused_x1 = softmax(attn @ x2)  [256,300], K=256
    {
        int tiles = ceil_div(B_, 16);            // 16
        int tps = 2;                              // -> 8 splits
        dim3 grid(ceil_div(E_, 64), B_ / 64, ceil_div(tiles, tps));  // 5x4x8 = 160
        sgemm_splitk_kernel<0, 0, 0><<<grid, 256>>>(
            p_attn, mol_repr, nullptr, p_f1, B_, E_, B_, B_, E_, tps);
        row_softmax_kernel<<<B_, 256>>>(p_f1, E_);
    }

    // 7) fused_x2 = softmax(attn^T @ x1)  [256,1280], K=256
    {
        int tiles = ceil_div(B_, 16);            // 16
        int tps = 4;                              // -> 4 splits
        dim3 grid(D_ / 64, B_ / 64, ceil_div(tiles, tps));  // 20x4x4 = 320
        sgemm_splitk_kernel<1, 0, 0><<<grid, 256>>>(
            p_attn, p_x1, nullptr, p_f2, B_, D_, B_, B_, D_, tps);
        row_softmax_kernel<<<B_, 256>>>(p_f2, D_);
    }

    // 8) combined = [x1*(f2+1), x2*(f1+1)]  [256,1580]
    combine_kernel<<<ceil_div(B_ * C_, 256), 256>>>(mol_repr);

    // 9) h = combined @ W_fc1  [256,256], K=1580 (bias+relu folded into final)
    {
        int tiles = ceil_div(C_, 16);            // 99
        int tps = 7;                              // -> 15 splits
        dim3 grid(H_ / 64, B_ / 64, ceil_div(tiles, tps));  // 4x4x15 = 240
        sgemm_splitk_kernel<0, 0, 0><<<grid, 256>>>(
            p_comb, W_fc1, nullptr, p_h, B_, H_, C_, C_, H_, tps);
    }

    // 10) out = relu(h + b_fc1) @ W_fc2 + b_fc2  [256,1]
    final_kernel<<<B_, 256>>>(b_fc1, W_fc2, b_fc2, out);
}

// round 4
// speedup vs baseline: 2.2412x; 1.0443x over previous
#include <cuda_runtime.h>
#include <cuda_bf16.h>

#define B_ 256
#define L_ 1026
#define D_ 1280
#define E_ 300
#define H_ 256
#define C_ 1580   // D_+E_

// ---- scratch (device globals; no allocation allowed) ----
__device__ float g_pooled[B_ * D_];
__device__ float g_inv[B_];
__device__ float g_x1[B_ * D_];
__device__ float g_q[B_ * E_];
__device__ float g_attn[B_ * B_];
__device__ float g_f1[B_ * E_];
__device__ float g_f2[B_ * D_];
__device__ float g_comb[B_ * C_];
__device__ float g_h[B_ * H_];

// ------------------------------------------------------------------
// init all accumulators in one pass:
//   pooled/f1/f2/attn/h <- 0 ; x1 <- b_prot (bcast) ; q <- b_attn (bcast)
//   inv[b] <- 1/max(len-2,1)
// ------------------------------------------------------------------
__global__ void init_all_kernel(const int* __restrict__ lens,
                                const float* __restrict__ b_prot,
                                const float* __restrict__ b_attn) {
    int i = blockIdx.x * blockDim.x + threadIdx.x;
    if (i < B_ * D_) {
        g_pooled[i] = 0.f;
        g_f2[i] = 0.f;
        g_x1[i] = b_prot[i % D_];
    }
    if (i < B_ * E_) {
        g_f1[i] = 0.f;
        g_q[i] = b_attn[i % E_];
    }
    if (i < B_ * B_) g_attn[i] = 0.f;
    if (i < B_ * H_) g_h[i] = 0.f;
    if (i < B_) {
        int len = lens[i];
        g_inv[i] = 1.f / fmaxf((float)(len - 2), 1.f);
    }
}

// ------------------------------------------------------------------
// ragged masked sum pooling: grid (B, ceil(L/TL)), block 320 (= D/4)
// ------------------------------------------------------------------
#define TL 128
__global__ void pool_kernel(const float* __restrict__ tok,
                            const int* __restrict__ lens) {
    int b = blockIdx.x;
    int len = lens[b];
    int l0 = blockIdx.y * TL;
    if (l0 < 1) l0 = 1;
    int l1 = min((int)(blockIdx.y + 1) * TL, len - 1);
    if (l0 >= l1) return;

    int d4 = threadIdx.x;  // 0..319
    const float4* base = reinterpret_cast<const float4*>(tok)
                       + (size_t)b * L_ * (D_ / 4) + d4;
    float4 acc = make_float4(0.f, 0.f, 0.f, 0.f);
    for (int l = l0; l < l1; l++) {
        float4 v = base[(size_t)l * (D_ / 4)];
        acc.x += v.x; acc.y += v.y; acc.z += v.z; acc.w += v.w;
    }
    float* o = g_pooled + b * D_ + d4 * 4;
    atomicAdd(o + 0, acc.x);
    atomicAdd(o + 1, acc.y);
    atomicAdd(o + 2, acc.z);
    atomicAdd(o + 3, acc.w);
}

// ------------------------------------------------------------------
// split-K tiled SGEMM, partials accumulated via atomicAdd into C.
//   C[M,N] += sum_{k in split} (SCALEA? rscale[m]:1) * A_eff(m,k)*B_eff(k,n)
// BM=BN=64, BK=16, 256 threads, 4x4 microtile.
// C pre-initialized (zero or bias).
// ------------------------------------------------------------------
template <int TA, int TB, int SCALEA>
__global__ void sgemm_splitk_kernel(const float* __restrict__ A,
                                    const float* __restrict__ B,
                                    const float* __restrict__ rscale,
                                    float* __restrict__ C,
                                    int M, int N, int K, int lda, int ldb,
                                    int tiles_per_split) {
    __shared__ float As[16][64];
    __shared__ float Bs[16][64];

    int k_begin = blockIdx.z * tiles_per_split * 16;
    if (k_begin >= K) return;
    int k_end = min(k_begin + tiles_per_split * 16, K);

    int t = threadIdx.x;
    int bm = blockIdx.y * 64;
    int bn = blockIdx.x * 64;
    int tx = t & 15;   // N dir
    int ty = t >> 4;   // M dir

    float acc[4][4];
#pragma unroll
    for (int i = 0; i < 4; i++)
#pragma unroll
        for (int j = 0; j < 4; j++) acc[i][j] = 0.f;

    for (int k0 = k_begin; k0 < k_end; k0 += 16) {
        if (!TA) {
            int mm = t >> 2;
            int kk4 = (t & 3) * 4;
            float4 v = make_float4(0.f, 0.f, 0.f, 0.f);
            if (k0 + kk4 < K)
                v = *reinterpret_cast<const float4*>(
                        &A[(size_t)(bm + mm) * lda + k0 + kk4]);
            As[kk4 + 0][mm] = v.x;
            As[kk4 + 1][mm] = v.y;
            As[kk4 + 2][mm] = v.z;
            As[kk4 + 3][mm] = v.w;
        } else {
            int kk = t >> 4;
            int mm4 = (t & 15) * 4;
            float4 v = make_float4(0.f, 0.f, 0.f, 0.f);
            if (k0 + kk < K)
                v = *reinterpret_cast<const float4*>(
                        &A[(size_t)(k0 + kk) * lda + bm + mm4]);
            *reinterpret_cast<float4*>(&As[kk][mm4]) = v;
        }
        if (!TB) {
            int kk = t >> 4;
            int nn4 = (t & 15) * 4;
            float4 v = make_float4(0.f, 0.f, 0.f, 0.f);
            if (k0 + kk < K && bn + nn4 < N)
                v = *reinterpret_cast<const float4*>(
                        &B[(size_t)(k0 + kk) * ldb + bn + nn4]);
            *reinterpret_cast<float4*>(&Bs[kk][nn4]) = v;
        } else {
            int nn = t >> 2;
            int kk4 = (t & 3) * 4;
            float4 v = make_float4(0.f, 0.f, 0.f, 0.f);
            if (bn + nn < N && k0 + kk4 < K)
                v = *reinterpret_cast<const float4*>(
                        &B[(size_t)(bn + nn) * ldb + k0 + kk4]);
            Bs[kk4 + 0][nn] = v.x;
            Bs[kk4 + 1][nn] = v.y;
            Bs[kk4 + 2][nn] = v.z;
            Bs[kk4 + 3][nn] = v.w;
        }
        __syncthreads();

#pragma unroll
        for (int kk = 0; kk < 16; kk++) {
            float4 av = *reinterpret_cast<float4*>(&As[kk][ty * 4]);
            float4 bv = *reinterpret_cast<float4*>(&Bs[kk][tx * 4]);
            float a[4] = {av.x, av.y, av.z, av.w};
            float b[4] = {bv.x, bv.y, bv.z, bv.w};
#pragma unroll
            for (int i = 0; i < 4; i++)
#pragma unroll
                for (int j = 0; j < 4; j++) acc[i][j] += a[i] * b[j];
        }
        __syncthreads();
    }

#pragma unroll
    for (int i = 0; i < 4; i++) {
        int gm = bm + ty * 4 + i;
        float sc = SCALEA ? rscale[gm] : 1.f;
#pragma unroll
        for (int j = 0; j < 4; j++) {
            int gn = bn + tx * 4 + j;
            if (gn < N) atomicAdd(&C[(size_t)gm * N + gn], acc[i][j] * sc);
        }
    }
}

// ------------------------------------------------------------------
// relu in place over N4 float4 elements
// ------------------------------------------------------------------
__global__ void relu4_kernel(float4* __restrict__ X, int N4) {
    int i = blockIdx.x * blockDim.x + threadIdx.x;
    if (i >= N4) return;
    float4 v = X[i];
    v.x = fmaxf(v.x, 0.f); v.y = fmaxf(v.y, 0.f);
    v.z = fmaxf(v.z, 0.f); v.w = fmaxf(v.w, 0.f);
    X[i] = v;
}

// ------------------------------------------------------------------
// row softmax in-place: one block (256 threads) per row
// ------------------------------------------------------------------
__global__ void row_softmax_kernel(float* __restrict__ X, int N) {
    int r = blockIdx.x;
    float* x = X + (size_t)r * N;
    int t = threadIdx.x;
    __shared__ float red[8];

    float m = -1e30f;
    for (int i = t; i < N; i += 256) m = fmaxf(m, x[i]);
#pragma unroll
    for (int o = 16; o > 0; o >>= 1) m = fmaxf(m, __shfl_xor_sync(0xffffffffu, m, o));
    if ((t & 31) == 0) red[t >> 5] = m;
    __syncthreads();
    if (t < 8) {
        float v = red[t];
#pragma unroll
        for (int o = 4; o > 0; o >>= 1) v = fmaxf(v, __shfl_xor_sync(0xffu, v, o));
        if (t == 0) red[0] = v;
    }
    __syncthreads();
    m = red[0];
    __syncthreads();

    float s = 0.f;
    for (int i = t; i < N; i += 256) {
        float e = __expf(x[i] - m);
        x[i] = e;
        s += e;
    }
#pragma unroll
    for (int o = 16; o > 0; o >>= 1) s += __shfl_xor_sync(0xffffffffu, s, o);
    if ((t & 31) == 0) red[t >> 5] = s;
    __syncthreads();
    if (t < 8) {
        float v = red[t];
#pragma unroll
        for (int o = 4; o > 0; o >>= 1) v += __shfl_xor_sync(0xffu, v, o);
        if (t == 0) red[0] = v;
    }
    __syncthreads();
    float inv = 1.f / red[0];
    for (int i = t; i < N; i += 256) x[i] *= inv;
}

// ------------------------------------------------------------------
// fused per-row: softmax(F row of width N) then
//   comb[r*C + off + j] = base[r*N + j] * (softmaxed + 1)
// one block (256 threads) per row, F modified in place (exp stage).
// ------------------------------------------------------------------
__global__ void softmax_combine_kernel(float* __restrict__ F,
                                       const float* __restrict__ base,
                                       int N, int off) {
    int r = blockIdx.x;
    float* x = F + (size_t)r * N;
    const float* bs = base + (size_t)r * N;
    float* cb = g_comb + (size_t)r * C_ + off;
    int t = threadIdx.x;
    __shared__ float red[8];

    float m = -1e30f;
    for (int i = t; i < N; i += 256) m = fmaxf(m, x[i]);
#pragma unroll
    for (int o = 16; o > 0; o >>= 1) m = fmaxf(m, __shfl_xor_sync(0xffffffffu, m, o));
    if ((t & 31) == 0) red[t >> 5] = m;
    __syncthreads();
    if (t < 8) {
        float v = red[t];
#pragma unroll
        for (int o = 4; o > 0; o >>= 1) v = fmaxf(v, __shfl_xor_sync(0xffu, v, o));
        if (t == 0) red[0] = v;
    }
    __syncthreads();
    m = red[0];
    __syncthreads();

    float s = 0.f;
    for (int i = t; i < N; i += 256) {
        float e = __expf(x[i] - m);
        x[i] = e;
        s += e;
    }
#pragma unroll
    for (int o = 16; o > 0; o >>= 1) s += __shfl_xor_sync(0xffffffffu, s, o);
    if ((t & 31) == 0) red[t >> 5] = s;
    __syncthreads();
    if (t < 8) {
        float v = red[t];
#pragma unroll
        for (int o = 4; o > 0; o >>= 1) v += __shfl_xor_sync(0xffu, v, o);
        if (t == 0) red[0] = v;
    }
    __syncthreads();
    float inv = 1.f / red[0];
    for (int i = t; i < N; i += 256)
        cb[i] = bs[i] * (x[i] * inv + 1.f);
}

// ------------------------------------------------------------------
// out[b] = sum_h relu(g_h[b,h] + b_fc1[h]) * W2[h] + b2[0]
// ------------------------------------------------------------------
__global__ void final_kernel(const float* __restrict__ b1,
                             const float* __restrict__ W2,
                             const float* __restrict__ b2,
                             float* __restrict__ out) {
    int b = blockIdx.x;
    int t = threadIdx.x;
    __shared__ float red[8];
    float v = fmaxf(g_h[b * H_ + t] + b1[t], 0.f) * W2[t];
#pragma unroll
    for (int o = 16; o > 0; o >>= 1) v += __shfl_xor_sync(0xffffffffu, v, o);
    if ((t & 31) == 0) red[t >> 5] = v;
    __syncthreads();
    if (t < 8) {
        float s = red[t];
#pragma unroll
        for (int o = 4; o > 0; o >>= 1) s += __shfl_xor_sync(0xffu, s, o);
        if (t == 0) out[b] = s + b2[0];
    }
}

// ------------------------------------------------------------------
static inline int ceil_div(int a, int b) { return (a + b - 1) / b; }

extern "C" void kernel_launch(void* const* d_in, const int* in_sizes, int n_in,
                              void* d_out, int out_size) {
    const float* token_reps = (const float*)d_in[0];
    const int*   batch_lens = (const int*)d_in[1];
    const float* mol_repr   = (const float*)d_in[2];
    const float* W_prot     = (const float*)d_in[3];
    const float* b_prot     = (const float*)d_in[4];
    const float* W_attn     = (const float*)d_in[5];
    const float* b_attn     = (const float*)d_in[6];
    const float* W_fc1      = (const float*)d_in[7];
    const float* b_fc1      = (const float*)d_in[8];
    const float* W_fc2      = (const float*)d_in[9];
    const float* b_fc2      = (const float*)d_in[10];
    float* out = (float*)d_out;

    float *p_pooled, *p_inv, *p_x1, *p_q, *p_attn, *p_f1, *p_f2, *p_comb, *p_h;
    cudaGetSymbolAddress((void**)&p_pooled, g_pooled);
    cudaGetSymbolAddress((void**)&p_inv,    g_inv);
    cudaGetSymbolAddress((void**)&p_x1,     g_x1);
    cudaGetSymbolAddress((void**)&p_q,      g_q);
    cudaGetSymbolAddress((void**)&p_attn,   g_attn);
    cudaGetSymbolAddress((void**)&p_f1,     g_f1);
    cudaGetSymbolAddress((void**)&p_f2,     g_f2);
    cudaGetSymbolAddress((void**)&p_comb,   g_comb);
    cudaGetSymbolAddress((void**)&p_h,      g_h);

    // 1) init accumulators (biases folded in) + inverse counts
    init_all_kernel<<<ceil_div(B_ * D_, 256), 256>>>(batch_lens, b_prot, b_attn);

    // 2) ragged masked sum pool
    {
        dim3 grid(B_, ceil_div(L_, TL));
        pool_kernel<<<grid, D_ / 4>>>(token_reps, batch_lens);
    }

    // 3) x1 = relu((pooled/count) @ W_prot + b_prot)  [256,1280], K=1280
    {
        int tiles = ceil_div(D_, 16);            // 80
        int tps = 16;                            // -> 5 splits
        dim3 grid(D_ / 64, B_ / 64, ceil_div(tiles, tps));   // 20x4x5 = 400
        sgemm_splitk_kernel<0, 0, 1><<<grid, 256>>>(
            p_pooled, W_prot, p_inv, p_x1, B_, D_, D_, D_, D_, tps);
        relu4_kernel<<<ceil_div(B_ * D_ / 4, 256), 256>>>(
            (float4*)p_x1, B_ * D_ / 4);
    }

    // 4) q = x1 @ W_attn + b_attn  [256,300], K=1280 (bias pre-loaded)
    {
        int tiles = ceil_div(D_, 16);            // 80
        int tps = 8;                             // -> 10 splits
        dim3 grid(ceil_div(E_, 64), B_ / 64, ceil_div(tiles, tps));  // 5x4x10 = 200
        sgemm_splitk_kernel<0, 0, 0><<<grid, 256>>>(
            p_x1, W_attn, nullptr, p_q, B_, E_, D_, D_, E_, tps);
    }

    // 5) attn = softmax(q @ x2^T)  [256,256], K=300
    {
        int tiles = ceil_div(E_, 16);            // 19
        int tps = 2;                             // -> 10 splits
        dim3 grid(B_ / 64, B_ / 64, ceil_div(tiles, tps));  // 4x4x10 = 160
        sgemm_splitk_kernel<0, 1, 0><<<grid, 256>>>(
            p_q, mol_repr, nullptr, p_attn, B_, B_, E_, E_, E_, tps);
        row_softmax_kernel<<<B_, 256>>>(p_attn, B_);
    }

    // 6) f1 = attn @ x2  [256,300], K=256; then comb[:,D:] = x2*(softmax(f1)+1)
    {
        int tiles = ceil_div(B_, 16);            // 16
        int tps = 2;                             // -> 8 splits
        dim3 grid(ceil_div(E_, 64), B_ / 64, ceil_div(tiles, tps));  // 5x4x8 = 160
        sgemm_splitk_kernel<0, 0, 0><<<grid, 256>>>(
            p_attn, mol_repr, nullptr, p_f1, B_, E_, B_, B_, E_, tps);
        softmax_combine_kernel<<<B_, 256>>>(p_f1, mol_repr, E_, D_);
    }

    // 7) f2 = attn^T @ x1  [256,1280], K=256; then comb[:,:D] = x1*(softmax(f2)+1)
    {
        int tiles = ceil_div(B_, 16);            // 16
        int tps = 4;                             // -> 4 splits
        dim3 grid(D_ / 64, B_ / 64, ceil_div(tiles, tps));  // 20x4x4 = 320
        sgemm_splitk_kernel<1, 0, 0><<<grid, 256>>>(
            p_attn, p_x1, nullptr, p_f2, B_, D_, B_, B_, D_, tps);
        softmax_combine_kernel<<<B_, 256>>>(p_f2, p_x1, D_, 0);
    }

    // 8) h = combined @ W_fc1  [256,256], K=1580 (bias+relu folded into final)
    {
        int tiles = ceil_div(C_, 16);            // 99
        int tps = 5;                             // -> 20 splits
        dim3 grid(H_ / 64, B_ / 64, ceil_div(tiles, tps));  // 4x4x20 = 320
        sgemm_splitk_kernel<0, 0, 0><<<grid, 256>>>(
            p_comb, W_fc1, nullptr, p_h, B_, H_, C_, C_, H_, tps);
    }

    // 9) out = relu(h + b_fc1) @ W_fc2 + b_fc2  [256,1]
    final_kernel<<<B_, 256>>>(b_fc1, W_fc2, b_fc2, out);
}

// round 6
// speedup vs baseline: 2.4729x; 1.1034x over previous
#include <cuda_runtime.h>
#include <cuda_bf16.h>
#include <mma.h>

using namespace nvcuda;

#define B_ 256
#define L_ 1026
#define D_ 1280
#define E_ 300
#define H_ 256
#define C_ 1580   // D_+E_

// SMEM layouts for the wmma GEMM
#define A_LD 20   // As[64][20]  (m-major, padded)
#define B_LD 68   // Bs[16][68]  (k-major, padded)

// ---- scratch (device globals; no allocation allowed) ----
__device__ float g_pooled[B_ * D_];
__device__ float g_inv[B_];
__device__ float g_x1[B_ * D_];
__device__ float g_q[B_ * E_];
__device__ float g_attn[B_ * B_];
__device__ float g_f1[B_ * E_];
__device__ float g_f2[B_ * D_];
__device__ float g_comb[B_ * C_];
__device__ float g_h[B_ * H_];

// ------------------------------------------------------------------
// init all accumulators in one pass:
//   pooled/f1/f2/attn/h <- 0 ; x1 <- b_prot (bcast) ; q <- b_attn (bcast)
//   inv[b] <- 1/max(len-2,1)
// ------------------------------------------------------------------
__global__ void init_all_kernel(const int* __restrict__ lens,
                                const float* __restrict__ b_prot,
                                const float* __restrict__ b_attn) {
    int i = blockIdx.x * blockDim.x + threadIdx.x;
    if (i < B_ * D_) {
        g_pooled[i] = 0.f;
        g_f2[i] = 0.f;
        g_x1[i] = b_prot[i % D_];
    }
    if (i < B_ * E_) {
        g_f1[i] = 0.f;
        g_q[i] = b_attn[i % E_];
    }
    if (i < B_ * B_) g_attn[i] = 0.f;
    if (i < B_ * H_) g_h[i] = 0.f;
    if (i < B_) {
        int len = lens[i];
        g_inv[i] = 1.f / fmaxf((float)(len - 2), 1.f);
    }
}

// ------------------------------------------------------------------
// ragged masked sum pooling: grid (B, ceil(L/TL)), block 320 (= D/4)
// ------------------------------------------------------------------
#define TL 128
__global__ void pool_kernel(const float* __restrict__ tok,
                            const int* __restrict__ lens) {
    int b = blockIdx.x;
    int len = lens[b];
    int l0 = blockIdx.y * TL;
    if (l0 < 1) l0 = 1;
    int l1 = min((int)(blockIdx.y + 1) * TL, len - 1);
    if (l0 >= l1) return;

    int d4 = threadIdx.x;  // 0..319
    const float4* base = reinterpret_cast<const float4*>(tok)
                       + (size_t)b * L_ * (D_ / 4) + d4;
    float4 acc = make_float4(0.f, 0.f, 0.f, 0.f);
    for (int l = l0; l < l1; l++) {
        float4 v = base[(size_t)l * (D_ / 4)];
        acc.x += v.x; acc.y += v.y; acc.z += v.z; acc.w += v.w;
    }
    float* o = g_pooled + b * D_ + d4 * 4;
    atomicAdd(o + 0, acc.x);
    atomicAdd(o + 1, acc.y);
    atomicAdd(o + 2, acc.z);
    atomicAdd(o + 3, acc.w);
}

// ------------------------------------------------------------------
// split-K tf32 wmma GEMM, partials accumulated via atomicAdd into C.
//   C[M,N] += sum_{k in split} (SCALEA? rscale[m]:1) * A_eff(m,k)*B_eff(k,n)
//   A_eff(m,k) = TA ? A[k*lda+m] : A[m*lda+k]
//   B_eff(k,n) = TB ? B[n*ldb+k] : B[k*ldb+n]
// BM=BN=64, BK=16, 256 threads (8 warps, 2x4). C pre-initialized.
// smem: staging needs 1280+1088=2368 floats; epilogue needs 8*512=4096.
// ------------------------------------------------------------------
template <int TA, int TB, int SCALEA>
__global__ void gemm_tf32_splitk_kernel(const float* __restrict__ A,
                                        const float* __restrict__ B,
                                        const float* __restrict__ rscale,
                                        float* __restrict__ C,
                                        int M, int N, int K, int lda, int ldb,
                                        int tiles_per_split) {
    __shared__ float smem[4096];   // 16 KB: max(staging 2368, epilogue 4096)
    float* As = smem;              // [64][A_LD]
    float* Bs = smem + 1280;       // [16][B_LD]

    int k_begin = blockIdx.z * tiles_per_split * 16;
    if (k_begin >= K) return;
    int k_end = min(k_begin + tiles_per_split * 16, K);

    int t = threadIdx.x;
    int bm = blockIdx.y * 64;
    int bn = blockIdx.x * 64;
    int wid = t >> 5;
    int warp_m = wid & 1;   // 0..1 -> 32 rows each
    int warp_n = wid >> 1;  // 0..3 -> 16 cols each

    wmma::fragment<wmma::accumulator, 16, 16, 8, float> cf[2];
    wmma::fill_fragment(cf[0], 0.f);
    wmma::fill_fragment(cf[1], 0.f);

    for (int k0 = k_begin; k0 < k_end; k0 += 16) {
        // ---- stage A tile -> As[m][k] ----
        if (!TA) {
            int mm = t >> 2;
            int kk4 = (t & 3) * 4;
            float4 v = make_float4(0.f, 0.f, 0.f, 0.f);
            if (k0 + kk4 < K)
                v = *reinterpret_cast<const float4*>(
                        &A[(size_t)(bm + mm) * lda + k0 + kk4]);
            *reinterpret_cast<float4*>(&As[mm * A_LD + kk4]) = v;
        } else {
            int kk = t >> 4;
            int mm4 = (t & 15) * 4;
            float4 v = make_float4(0.f, 0.f, 0.f, 0.f);
            if (k0 + kk < K)
                v = *reinterpret_cast<const float4*>(
                        &A[(size_t)(k0 + kk) * lda + bm + mm4]);
            As[(mm4 + 0) * A_LD + kk] = v.x;
            As[(mm4 + 1) * A_LD + kk] = v.y;
            As[(mm4 + 2) * A_LD + kk] = v.z;
            As[(mm4 + 3) * A_LD + kk] = v.w;
        }
        // ---- stage B tile -> Bs[k][n] ----
        if (!TB) {
            int kk = t >> 4;
            int nn4 = (t & 15) * 4;
            float4 v = make_float4(0.f, 0.f, 0.f, 0.f);
            if (k0 + kk < K && bn + nn4 < N)
                v = *reinterpret_cast<const float4*>(
                        &B[(size_t)(k0 + kk) * ldb + bn + nn4]);
            *reinterpret_cast<float4*>(&Bs[kk * B_LD + nn4]) = v;
        } else {
            int nn = t >> 2;
            int kk4 = (t & 3) * 4;
            float4 v = make_float4(0.f, 0.f, 0.f, 0.f);
            if (bn + nn < N && k0 + kk4 < K)
                v = *reinterpret_cast<const float4*>(
                        &B[(size_t)(bn + nn) * ldb + k0 + kk4]);
            Bs[(kk4 + 0) * B_LD + nn] = v.x;
            Bs[(kk4 + 1) * B_LD + nn] = v.y;
            Bs[(kk4 + 2) * B_LD + nn] = v.z;
            Bs[(kk4 + 3) * B_LD + nn] = v.w;
        }
        __syncthreads();

#pragma unroll
        for (int kk = 0; kk < 16; kk += 8) {
            wmma::fragment<wmma::matrix_b, 16, 16, 8,
                           wmma::precision::tf32, wmma::row_major> bf;
            wmma::load_matrix_sync(bf, &Bs[kk * B_LD + warp_n * 16], B_LD);
#pragma unroll
            for (int i = 0; i < bf.num_elements; i++)
                bf.x[i] = wmma::__float_to_tf32(bf.x[i]);
#pragma unroll
            for (int ma = 0; ma < 2; ma++) {
                wmma::fragment<wmma::matrix_a, 16, 16, 8,
                               wmma::precision::tf32, wmma::row_major> af;
                wmma::load_matrix_sync(
                    af, &As[(warp_m * 32 + ma * 16) * A_LD + kk], A_LD);
#pragma unroll
                for (int i = 0; i < af.num_elements; i++)
                    af.x[i] = wmma::__float_to_tf32(af.x[i]);
                wmma::mma_sync(cf[ma], af, bf, cf[ma]);
            }
        }
        __syncthreads();
    }

    // ---- epilogue: stage fragments to SMEM, then atomicAdd to C ----
    float* epi = smem + wid * 512;  // 2 fragments x 256 per warp (fits: 8*512=4096)
    wmma::store_matrix_sync(epi, cf[0], 16, wmma::mem_row_major);
    wmma::store_matrix_sync(epi + 256, cf[1], 16, wmma::mem_row_major);
    __syncwarp();

    int lane = t & 31;
    for (int idx = lane; idx < 512; idx += 32) {
        int ma = idx >> 8;
        int r = (idx & 255) >> 4;
        int c = idx & 15;
        int gm = bm + warp_m * 32 + ma * 16 + r;
        int gn = bn + warp_n * 16 + c;
        if (gn < N) {
            float v = epi[ma * 256 + r * 16 + c];
            if (SCALEA) v *= rscale[gm];
            atomicAdd(&C[(size_t)gm * N + gn], v);
        }
    }
}

// ------------------------------------------------------------------
// relu in place over N4 float4 elements
// ------------------------------------------------------------------
__global__ void relu4_kernel(float4* __restrict__ X, int N4) {
    int i = blockIdx.x * blockDim.x + threadIdx.x;
    if (i >= N4) return;
    float4 v = X[i];
    v.x = fmaxf(v.x, 0.f); v.y = fmaxf(v.y, 0.f);
    v.z = fmaxf(v.z, 0.f); v.w = fmaxf(v.w, 0.f);
    X[i] = v;
}

// ------------------------------------------------------------------
// row softmax in-place: one block (256 threads) per row
// ------------------------------------------------------------------
__global__ void row_softmax_kernel(float* __restrict__ X, int N) {
    int r = blockIdx.x;
    float* x = X + (size_t)r * N;
    int t = threadIdx.x;
    __shared__ float red[8];

    float m = -1e30f;
    for (int i = t; i < N; i += 256) m = fmaxf(m, x[i]);
#pragma unroll
    for (int o = 16; o > 0; o >>= 1) m = fmaxf(m, __shfl_xor_sync(0xffffffffu, m, o));
    if ((t & 31) == 0) red[t >> 5] = m;
    __syncthreads();
    if (t < 8) {
        float v = red[t];
#pragma unroll
        for (int o = 4; o > 0; o >>= 1) v = fmaxf(v, __shfl_xor_sync(0xffu, v, o));
        if (t == 0) red[0] = v;
    }
    __syncthreads();
    m = red[0];
    __syncthreads();

    float s = 0.f;
    for (int i = t; i < N; i += 256) {
        float e = __expf(x[i] - m);
        x[i] = e;
        s += e;
    }
#pragma unroll
    for (int o = 16; o > 0; o >>= 1) s += __shfl_xor_sync(0xffffffffu, s, o);
    if ((t & 31) == 0) red[t >> 5] = s;
    __syncthreads();
    if (t < 8) {
        float v = red[t];
#pragma unroll
        for (int o = 4; o > 0; o >>= 1) v += __shfl_xor_sync(0xffu, v, o);
        if (t == 0) red[0] = v;
    }
    __syncthreads();
    float inv = 1.f / red[0];
    for (int i = t; i < N; i += 256) x[i] *= inv;
}

// ------------------------------------------------------------------
// fused per-row: softmax(F row of width N) then
//   comb[r*C + off + j] = base[r*N + j] * (softmaxed + 1)
// ------------------------------------------------------------------
__global__ void softmax_combine_kernel(float* __restrict__ F,
                                       const float* __restrict__ base,
                                       int N, int off) {
    int r = blockIdx.x;
    float* x = F + (size_t)r * N;
    const float* bs = base + (size_t)r * N;
    float* cb = g_comb + (size_t)r * C_ + off;
    int t = threadIdx.x;
    __shared__ float red[8];

    float m = -1e30f;
    for (int i = t; i < N; i += 256) m = fmaxf(m, x[i]);
#pragma unroll
    for (int o = 16; o > 0; o >>= 1) m = fmaxf(m, __shfl_xor_sync(0xffffffffu, m, o));
    if ((t & 31) == 0) red[t >> 5] = m;
    __syncthreads();
    if (t < 8) {
        float v = red[t];
#pragma unroll
        for (int o = 4; o > 0; o >>= 1) v = fmaxf(v, __shfl_xor_sync(0xffu, v, o));
        if (t == 0) red[0] = v;
    }
    __syncthreads();
    m = red[0];
    __syncthreads();

    float s = 0.f;
    for (int i = t; i < N; i += 256) {
        float e = __expf(x[i] - m);
        x[i] = e;
        s += e;
    }
#pragma unroll
    for (int o = 16; o > 0; o >>= 1) s += __shfl_xor_sync(0xffffffffu, s, o);
    if ((t & 31) == 0) red[t >> 5] = s;
    __syncthreads();
    if (t < 8) {
        float v = red[t];
#pragma unroll
        for (int o = 4; o > 0; o >>= 1) v += __shfl_xor_sync(0xffu, v, o);
        if (t == 0) red[0] = v;
    }
    __syncthreads();
    float inv = 1.f / red[0];
    for (int i = t; i < N; i += 256)
        cb[i] = bs[i] * (x[i] * inv + 1.f);
}

// ------------------------------------------------------------------
// out[b] = sum_h relu(g_h[b,h] + b_fc1[h]) * W2[h] + b2[0]
// ------------------------------------------------------------------
__global__ void final_kernel(const float* __restrict__ b1,
                             const float* __restrict__ W2,
                             const float* __restrict__ b2,
                             float* __restrict__ out) {
    int b = blockIdx.x;
    int t = threadIdx.x;
    __shared__ float red[8];
    float v = fmaxf(g_h[b * H_ + t] + b1[t], 0.f) * W2[t];
#pragma unroll
    for (int o = 16; o > 0; o >>= 1) v += __shfl_xor_sync(0xffffffffu, v, o);
    if ((t & 31) == 0) red[t >> 5] = v;
    __syncthreads();
    if (t < 8) {
        float s = red[t];
#pragma unroll
        for (int o = 4; o > 0; o >>= 1) s += __shfl_xor_sync(0xffu, s, o);
        if (t == 0) out[b] = s + b2[0];
    }
}

// ------------------------------------------------------------------
static inline int ceil_div(int a, int b) { return (a + b - 1) / b; }

extern "C" void kernel_launch(void* const* d_in, const int* in_sizes, int n_in,
                              void* d_out, int out_size) {
    const float* token_reps = (const float*)d_in[0];
    const int*   batch_lens = (const int*)d_in[1];
    const float* mol_repr   = (const float*)d_in[2];
    const float* W_prot     = (const float*)d_in[3];
    const float* b_prot     = (const float*)d_in[4];
    const float* W_attn     = (const float*)d_in[5];
    const float* b_attn     = (const float*)d_in[6];
    const float* W_fc1      = (const float*)d_in[7];
    const float* b_fc1      = (const float*)d_in[8];
    const float* W_fc2      = (const float*)d_in[9];
    const float* b_fc2      = (const float*)d_in[10];
    float* out = (float*)d_out;

    float *p_pooled, *p_inv, *p_x1, *p_q, *p_attn, *p_f1, *p_f2, *p_comb, *p_h;
    cudaGetSymbolAddress((void**)&p_pooled, g_pooled);
    cudaGetSymbolAddress((void**)&p_inv,    g_inv);
    cudaGetSymbolAddress((void**)&p_x1,     g_x1);
    cudaGetSymbolAddress((void**)&p_q,      g_q);
    cudaGetSymbolAddress((void**)&p_attn,   g_attn);
    cudaGetSymbolAddress((void**)&p_f1,     g_f1);
    cudaGetSymbolAddress((void**)&p_f2,     g_f2);
    cudaGetSymbolAddress((void**)&p_comb,   g_comb);
    cudaGetSymbolAddress((void**)&p_h,      g_h);

    // 1) init accumulators (biases folded in) + inverse counts
    init_all_kernel<<<ceil_div(B_ * D_, 256), 256>>>(batch_lens, b_prot, b_attn);

    // 2) ragged masked sum pool
    {
        dim3 grid(B_, ceil_div(L_, TL));
        pool_kernel<<<grid, D_ / 4>>>(token_reps, batch_lens);
    }

    // 3) x1 = relu((pooled/count) @ W_prot + b_prot)  [256,1280], K=1280
    {
        int tiles = ceil_div(D_, 16);            // 80
        int tps = 16;                            // -> 5 splits
        dim3 grid(D_ / 64, B_ / 64, ceil_div(tiles, tps));   // 20x4x5 = 400
        gemm_tf32_splitk_kernel<0, 0, 1><<<grid, 256>>>(
            p_pooled, W_prot, p_inv, p_x1, B_, D_, D_, D_, D_, tps);
        relu4_kernel<<<ceil_div(B_ * D_ / 4, 256), 256>>>(
            (float4*)p_x1, B_ * D_ / 4);
    }

    // 4) q = x1 @ W_attn + b_attn  [256,300], K=1280 (bias pre-loaded)
    {
        int tiles = ceil_div(D_, 16);            // 80
        int tps = 8;                             // -> 10 splits
        dim3 grid(ceil_div(E_, 64), B_ / 64, ceil_div(tiles, tps));  // 5x4x10 = 200
        gemm_tf32_splitk_kernel<0, 0, 0><<<grid, 256>>>(
            p_x1, W_attn, nullptr, p_q, B_, E_, D_, D_, E_, tps);
    }

    // 5) attn = softmax(q @ x2^T)  [256,256], K=300
    {
        int tiles = ceil_div(E_, 16);            // 19
        int tps = 2;                             // -> 10 splits
        dim3 grid(B_ / 64, B_ / 64, ceil_div(tiles, tps));  // 4x4x10 = 160
        gemm_tf32_splitk_kernel<0, 1, 0><<<grid, 256>>>(
            p_q, mol_repr, nullptr, p_attn, B_, B_, E_, E_, E_, tps);
        row_softmax_kernel<<<B_, 256>>>(p_attn, B_);
    }

    // 6) f1 = attn @ x2  [256,300], K=256; then comb[:,D:] = x2*(softmax(f1)+1)
    {
        int tiles = ceil_div(B_, 16);            // 16
        int tps = 2;                             // -> 8 splits
        dim3 grid(ceil_div(E_, 64), B_ / 64, ceil_div(tiles, tps));  // 5x4x8 = 160
        gemm_tf32_splitk_kernel<0, 0, 0><<<grid, 256>>>(
            p_attn, mol_repr, nullptr, p_f1, B_, E_, B_, B_, E_, tps);
        softmax_combine_kernel<<<B_, 256>>>(p_f1, mol_repr, E_, D_);
    }

    // 7) f2 = attn^T @ x1  [256,1280], K=256; then comb[:,:D] = x1*(softmax(f2)+1)
    {
        int tiles = ceil_div(B_, 16);            // 16
        int tps = 4;                             // -> 4 splits
        dim3 grid(D_ / 64, B_ / 64, ceil_div(tiles, tps));  // 20x4x4 = 320
        gemm_tf32_splitk_kernel<1, 0, 0><<<grid, 256>>>(
            p_attn, p_x1, nullptr, p_f2, B_, D_, B_, B_, D_, tps);
        softmax_combine_kernel<<<B_, 256>>>(p_f2, p_x1, D_, 0);
    }

    // 8) h = combined @ W_fc1  [256,256], K=1580 (bias+relu folded into final)
    {
        int tiles = ceil_div(C_, 16);            // 99
        int tps = 5;                             // -> 20 splits
        dim3 grid(H_ / 64, B_ / 64, ceil_div(tiles, tps));  // 4x4x20 = 320
        gemm_tf32_splitk_kernel<0, 0, 0><<<grid, 256>>>(
            p_comb, W_fc1, nullptr, p_h, B_, H_, C_, C_, H_, tps);
    }

    // 9) out = relu(h + b_fc1) @ W_fc2 + b_fc2  [256,1]
    final_kernel<<<B_, 256>>>(b_fc1, W_fc2, b_fc2, out);
}